// round 15
// baseline (speedup 1.0000x reference)
#include <cuda_runtime.h>
#include <cstdint>

// Problem constants (fixed shapes from setup_inputs)
#define TT 64
#define BB 4096
#define DD 32
#define HH 5
#define GG 20      // 4*H gates
#define VV 10
#define IN 128

#define BLK 256
#define NCHUNK (BB / BLK)           // 16 b-chunks
#define TGRID (TT / 2)              // 32 (two t per thread: t and t+32)

// Per-b precomputed terms, f4-packed for coalesced LDG.128:
//   g_hb*p[g4][b][4] = hb*[4*g4+j][b]   (i/f/o gate rows pre-scaled by 0.5)
//   g_c*p[b][4] = c[b][0..3],  g_c*s[b] = c[b][4]
__device__ float g_hb0p[5 * BB * 4];
__device__ float g_hb1p[5 * BB * 4];
__device__ float g_c0p[BB * 4];
__device__ float g_c0s[BB];
__device__ float g_c1p[BB * 4];
__device__ float g_c1s[BB];
__device__ float g_lut[3 * VV * GG];   // [j][v][g], i/f/o rows pre-scaled by 0.5

// gate g is a tanh (cell-candidate) gate iff 10 <= g < 15; others are sigmoids
__device__ __forceinline__ float gate_scale(int g) {
    return (g >= 2 * HH && g < 3 * HH) ? 1.0f : 0.5f;
}

// ---- fast activations: HW tanh (sm_75+) ----
__device__ __forceinline__ float tanh_fast(float v) {
    float r;
    asm("tanh.approx.f32 %0, %1;" : "=f"(r) : "f"(v));
    return r;
}
// sigmoid of the FULL gate value v, given the PRE-SCALED input v' = v/2:
// sigma(v) = 0.5*tanh(v/2) + 0.5
__device__ __forceinline__ float sigm_pre(float vh) {
    return fmaf(0.5f, tanh_fast(vh), 0.5f);
}

// ---------------------------------------------------------------------------
// Kernel 1: precompute. Blocks 0..79: one thread per (b, gate-quad):
// computes 4 gates of hb0 and hb1 (pre-scaled), writes one f4 each; the
// g4==0 thread also packs the cell state. Block 80: the embedding LUT.
// ---------------------------------------------------------------------------
__global__ void prep_kernel(const float* __restrict__ hidden,
                            const float* __restrict__ cell,
                            const float* __restrict__ embed,
                            const float* __restrict__ W_ih0,
                            const float* __restrict__ W_hh0,
                            const float* __restrict__ b_ih0,
                            const float* __restrict__ b_hh0,
                            const float* __restrict__ W_hh1,
                            const float* __restrict__ b_ih1,
                            const float* __restrict__ b_hh1) {
    if (blockIdx.x < 80) {
        int idx = blockIdx.x * BLK + threadIdx.x;   // 0..20479
        int b  = idx / 5;
        int g4 = idx - b * 5;                       // gate quad 0..4
        float h0[HH], h1[HH];
#pragma unroll
        for (int k = 0; k < HH; k++) {
            h0[k] = hidden[b * HH + k];
            h1[k] = hidden[BB * HH + b * HH + k];
        }
        float4 r0, r1;
        float* p0 = &r0.x;
        float* p1 = &r1.x;
#pragma unroll
        for (int j = 0; j < 4; j++) {
            int g = g4 * 4 + j;
            float s0 = b_ih0[g] + b_hh0[g];
            float s1 = b_ih1[g] + b_hh1[g];
#pragma unroll
            for (int k = 0; k < HH; k++) {
                s0 = fmaf(h0[k], W_hh0[g * HH + k], s0);
                s1 = fmaf(h1[k], W_hh1[g * HH + k], s1);
            }
            float sc = gate_scale(g);
            p0[j] = s0 * sc;
            p1[j] = s1 * sc;
        }
        ((float4*)g_hb0p)[g4 * BB + b] = r0;
        ((float4*)g_hb1p)[g4 * BB + b] = r1;

        if (g4 == 0) {
            float4 c0, c1;
            c0.x = cell[b * HH + 0]; c0.y = cell[b * HH + 1];
            c0.z = cell[b * HH + 2]; c0.w = cell[b * HH + 3];
            c1.x = cell[BB * HH + b * HH + 0]; c1.y = cell[BB * HH + b * HH + 1];
            c1.z = cell[BB * HH + b * HH + 2]; c1.w = cell[BB * HH + b * HH + 3];
            ((float4*)g_c0p)[b] = c0;
            ((float4*)g_c1p)[b] = c1;
            g_c0s[b] = cell[b * HH + 4];
            g_c1s[b] = cell[BB * HH + b * HH + 4];
        }
    } else {
        for (int i = threadIdx.x; i < 3 * VV * GG; i += BLK) {
            int j = i / (VV * GG);
            int r = i - j * (VV * GG);
            int v = r / GG;
            int g = r - v * GG;
            const float* e = embed + v * DD;
            const float* w = W_ih0 + g * IN + DD + DD * j;
            float s = 0.0f;
#pragma unroll
            for (int k = 0; k < DD; k++) s = fmaf(e[k], w[k], s);
            g_lut[i] = s * gate_scale(g);   // layout [j][v][g]
        }
    }
}

// ---------------------------------------------------------------------------
// Kernel 2: main. One thread per (b, {t, t+32}), register-interleaved dual-t.
// All sigmoid-gate inputs arrive pre-scaled by 0.5 -> sigmoid is MUFU+FFMA.
// Per-b terms load as f4 (5 LDG.128 for 20 gates).
//   blockIdx.x = b-chunk (16), blockIdx.y = t0 (32). 256 threads, 64-reg cap.
// ---------------------------------------------------------------------------
__global__ void __launch_bounds__(BLK, 4)
decoder_kernel(const float* __restrict__ dec_x,
               const int*   __restrict__ id1,
               const int*   __restrict__ id2,
               const int*   __restrict__ id3,
               const float* __restrict__ W_ih0,
               const float* __restrict__ W_ih1,
               float* __restrict__ out) {
    __shared__ __align__(16) float sWa[GG * DD];        // scaled W_ih0[:,0:32]
    __shared__ __align__(16) float sLut[3 * VV * GG];   // [j][v][g], 80B rows
    __shared__ __align__(16) float sW1t[HH * GG];       // scaled W_ih1^T [k][g]
    __shared__ __align__(16) float sOut[2 * BLK * HH];  // both items' staging

    const int tid = threadIdx.x;

    // ---- cooperative shared fill (with gate pre-scale on sigmoid rows) ----
    for (int i = tid; i < GG * DD; i += BLK) {
        int g = i >> 5, k = i & 31;
        sWa[i] = W_ih0[g * IN + k] * gate_scale(g);
    }
    for (int i = tid; i < HH * GG; i += BLK) {
        int k = i / GG, g = i - k * GG;
        sW1t[i] = W_ih1[g * HH + k] * gate_scale(g);
    }
    for (int i = tid; i < 3 * VV * GG; i += BLK) sLut[i] = g_lut[i];
    __syncthreads();

    const int b   = blockIdx.x * BLK + tid;
    const int t0  = blockIdx.y;                 // item 0: t0, item 1: t0+32
    const int tbA = t0 * BB + b;
    const int tbB = (t0 + TGRID) * BB + b;

    // ---- init both accumulators with hb0: 5 coalesced LDG.128 ----
    float acc[2][GG];
#pragma unroll
    for (int g4 = 0; g4 < 5; g4++) {
        float4 v = ((const float4*)g_hb0p)[g4 * BB + b];
        acc[0][4 * g4 + 0] = v.x; acc[1][4 * g4 + 0] = v.x;
        acc[0][4 * g4 + 1] = v.y; acc[1][4 * g4 + 1] = v.y;
        acc[0][4 * g4 + 2] = v.z; acc[1][4 * g4 + 2] = v.z;
        acc[0][4 * g4 + 3] = v.w; acc[1][4 * g4 + 3] = v.w;
    }

    // ---- embedding LUT adds per item (f4 over g) ----
#pragma unroll
    for (int it = 0; it < 2; it++) {
        const int tb = (it == 0) ? tbA : tbB;
        const int i1 = id1[tb], i2 = id2[tb], i3 = id3[tb];
        const float4* l1 = (const float4*)(sLut + (0 * VV + i1) * GG);
        const float4* l2 = (const float4*)(sLut + (1 * VV + i2) * GG);
        const float4* l3 = (const float4*)(sLut + (2 * VV + i3) * GG);
#pragma unroll
        for (int q = 0; q < GG / 4; q++) {
            float4 a = l1[q], c = l2[q], d = l3[q];
            acc[it][4 * q + 0] += a.x + c.x + d.x;
            acc[it][4 * q + 1] += a.y + c.y + d.y;
            acc[it][4 * q + 2] += a.z + c.z + d.z;
            acc[it][4 * q + 3] += a.w + c.w + d.w;
        }
    }

    // ---- dual-t GEMM: each weight LDS.128 feeds both items (8 FMA/load) ----
    {
        const float4* xpA = (const float4*)(dec_x + (size_t)tbA * DD);
        const float4* xpB = (const float4*)(dec_x + (size_t)tbB * DD);
#pragma unroll
        for (int q = 0; q < DD / 4; q++) {
            float4 xa = xpA[q];
            float4 xb = xpB[q];
            const float4* wp = (const float4*)sWa + q;   // stride DD/4 per gate
#pragma unroll
            for (int g = 0; g < GG; g++) {
                float4 w = wp[g * (DD / 4)];
                acc[0][g] = fmaf(xa.x, w.x, fmaf(xa.y, w.y,
                            fmaf(xa.z, w.z, fmaf(xa.w, w.w, acc[0][g]))));
                acc[1][g] = fmaf(xb.x, w.x, fmaf(xb.y, w.y,
                            fmaf(xb.z, w.z, fmaf(xb.w, w.w, acc[1][g]))));
            }
        }
    }

    // ---- LSTM cell 0 for BOTH items (c0: 1 LDG.128 + 1 LDG.32) ----
    float cc0[HH];
    {
        float4 cv = ((const float4*)g_c0p)[b];
        cc0[0] = cv.x; cc0[1] = cv.y; cc0[2] = cv.z; cc0[3] = cv.w;
        cc0[4] = g_c0s[b];
    }
    float h1[2][HH];
#pragma unroll
    for (int k = 0; k < HH; k++) {
#pragma unroll
        for (int it = 0; it < 2; it++) {
            float ig = sigm_pre(acc[it][k]);
            float fg = sigm_pre(acc[it][HH + k]);
            float gg = tanh_fast(acc[it][2 * HH + k]);
            float og = sigm_pre(acc[it][3 * HH + k]);
            float c  = fmaf(fg, cc0[k], ig * gg);
            h1[it][k] = og * tanh_fast(c);
        }
    }

    // ---- layer-1 gates for both items (hb1: 5 LDG.128) ----
    float a1[2][GG];
#pragma unroll
    for (int g4 = 0; g4 < 5; g4++) {
        float4 v = ((const float4*)g_hb1p)[g4 * BB + b];
        a1[0][4 * g4 + 0] = v.x; a1[1][4 * g4 + 0] = v.x;
        a1[0][4 * g4 + 1] = v.y; a1[1][4 * g4 + 1] = v.y;
        a1[0][4 * g4 + 2] = v.z; a1[1][4 * g4 + 2] = v.z;
        a1[0][4 * g4 + 3] = v.w; a1[1][4 * g4 + 3] = v.w;
    }
#pragma unroll
    for (int k = 0; k < HH; k++) {
        const float4* wp = (const float4*)(sW1t + k * GG);
#pragma unroll
        for (int q = 0; q < GG / 4; q++) {
            float4 w = wp[q];
#pragma unroll
            for (int it = 0; it < 2; it++) {
                float hv = h1[it][k];
                a1[it][4 * q + 0] = fmaf(hv, w.x, a1[it][4 * q + 0]);
                a1[it][4 * q + 1] = fmaf(hv, w.y, a1[it][4 * q + 1]);
                a1[it][4 * q + 2] = fmaf(hv, w.z, a1[it][4 * q + 2]);
                a1[it][4 * q + 3] = fmaf(hv, w.w, a1[it][4 * q + 3]);
            }
        }
    }

    // ---- LSTM cell 1 for both items (c1: 1 LDG.128 + 1 LDG.32) ----
    float cc1[HH];
    {
        float4 cv = ((const float4*)g_c1p)[b];
        cc1[0] = cv.x; cc1[1] = cv.y; cc1[2] = cv.z; cc1[3] = cv.w;
        cc1[4] = g_c1s[b];
    }
#pragma unroll
    for (int k = 0; k < HH; k++) {
#pragma unroll
        for (int it = 0; it < 2; it++) {
            float ig = sigm_pre(a1[it][k]);
            float fg = sigm_pre(a1[it][HH + k]);
            float gg = tanh_fast(a1[it][2 * HH + k]);
            float og = sigm_pre(a1[it][3 * HH + k]);
            float c  = fmaf(fg, cc1[k], ig * gg);
            sOut[it * BLK * HH + tid * HH + k] = og * tanh_fast(c);
        }
    }
    __syncthreads();

    // ---- coalesced store of both [256, 5] output slabs ----
    {
        float* obA = out + (size_t)t0 * BB * HH + (size_t)blockIdx.x * BLK * HH;
        float* obB = out + (size_t)(t0 + TGRID) * BB * HH
                         + (size_t)blockIdx.x * BLK * HH;
        for (int i = tid; i < BLK * HH; i += BLK) {
            obA[i] = sOut[i];
            obB[i] = sOut[BLK * HH + i];
        }
    }
}

// ---------------------------------------------------------------------------
// Launch
// Input order: 0 horizon, 1 hidden, 2 cell, 3 dec_x, 4 mote_id_cat,
// 5 fault_type_cat, 6 mote_fault_cat, 7 mote_embed, 8 W_ih0, 9 W_hh0,
// 10 b_ih0, 11 b_hh0, 12 W_ih1, 13 W_hh1, 14 b_ih1, 15 b_hh1
// ---------------------------------------------------------------------------
extern "C" void kernel_launch(void* const* d_in, const int* in_sizes, int n_in,
                              void* d_out, int out_size) {
    const float* hidden = (const float*)d_in[1];
    const float* cell   = (const float*)d_in[2];
    const float* dec_x  = (const float*)d_in[3];
    const int*   id1    = (const int*)d_in[4];
    const int*   id2    = (const int*)d_in[5];
    const int*   id3    = (const int*)d_in[6];
    const float* embed  = (const float*)d_in[7];
    const float* W_ih0  = (const float*)d_in[8];
    const float* W_hh0  = (const float*)d_in[9];
    const float* b_ih0  = (const float*)d_in[10];
    const float* b_hh0  = (const float*)d_in[11];
    const float* W_ih1  = (const float*)d_in[12];
    const float* W_hh1  = (const float*)d_in[13];
    const float* b_ih1  = (const float*)d_in[14];
    const float* b_hh1  = (const float*)d_in[15];
    float* out = (float*)d_out;

    prep_kernel<<<81, BLK>>>(hidden, cell, embed, W_ih0, W_hh0, b_ih0, b_hh0,
                             W_hh1, b_ih1, b_hh1);

    dim3 grid(NCHUNK, TGRID);
    decoder_kernel<<<grid, BLK>>>(dec_x, id1, id2, id3, W_ih0, W_ih1, out);
}